// round 16
// baseline (speedup 1.0000x reference)
#include <cuda_runtime.h>
#include <cuda_fp16.h>
#include <cstdint>

#define DEVINL __device__ __forceinline__

namespace {

constexpr int HDIM = 128;
constexpr long long BROWS = 131072;
constexpr long long BH = BROWS * (long long)HDIM;
constexpr int THREADS = 512;
constexpr int M_TILE = 32;
constexpr int NTILES = (int)(BROWS / M_TILE);  // 4096
constexpr int GRID = 148;                      // persistent: 1 CTA/SM
constexpr int CPAIR = GRID / 2;                // 74 CTAs per N-half

// smem word (uint32) offsets
constexpr int SW_BIAS = 0;                     // 256 words (this half's 4x64 biases)
constexpr int SW_A = 256;                      // packed A frags: 2bm*16ks*33 uint4
constexpr int A_WORDS = 2 * 16 * 33 * 4;       // 4224
constexpr int SW_RAW = SW_A + A_WORDS;         // 4480; 2 slots x 8192 words fp32
constexpr int RAW_SLOT = 8192;
constexpr int SW_B = SW_RAW + 2 * RAW_SLOT;    // 20864; resident B half image
constexpr int B_WORDS = 16 * 8 * 2 * 32 * 4;   // 32768 (128 KB fp16)
constexpr int SMEM_WORDS = SW_B + B_WORDS;     // 53632
constexpr int SMEM_BYTES = SMEM_WORDS * 4;     // 214528 -> 1 CTA/SM

// Pre-packed weights, fragment order:
// word idx = ((((half*16+ks)*8+wN)*2+gp)*32+lane)*4+wq
//   gp packs gates {2gp, 2gp+1}; wq = gsel*2 + bsel (b0/b1 k8-halves)
__device__ uint32_t g_wpack[2 * 16 * 8 * 2 * 32 * 4];  // 65536 words, 256 KB

DEVINL void cp16(uint32_t saddr, const void* gaddr) {
    asm volatile("cp.async.cg.shared.global [%0], [%1], 16;"
                 :: "r"(saddr), "l"(gaddr) : "memory");
}
DEVINL void cp_commit() { asm volatile("cp.async.commit_group;" ::: "memory"); }

DEVINL uint32_t packh2(float lo, float hi) {
    __half2 h = __floats2half2_rn(lo, hi);
    return *reinterpret_cast<uint32_t*>(&h);
}

DEVINL void mma16(float* d, const uint4& a, uint32_t b0, uint32_t b1) {
    asm volatile(
        "mma.sync.aligned.m16n8k16.row.col.f32.f16.f16.f32 "
        "{%0,%1,%2,%3}, {%4,%5,%6,%7}, {%8,%9}, {%0,%1,%2,%3};"
        : "+f"(d[0]), "+f"(d[1]), "+f"(d[2]), "+f"(d[3])
        : "r"(a.x), "r"(a.y), "r"(a.z), "r"(a.w), "r"(b0), "r"(b1));
}

DEVINL float sigf(float x) {
    return __fdividef(1.0f, 1.0f + __expf(-x));
}
DEVINL float tanhfast(float x) {
    return __fdividef(2.0f, 1.0f + __expf(-2.0f * x)) - 1.0f;
}

// Packed A word index for fp16x2 word holding (r,k),(r,k+1), k even; r 0..31.
// Consumer reads uint4 at ((bm*16 + ks)*33 + lane), bm = r>>4 in 0..1.
DEVINL int widx(int r, int k) {
    int bm = r >> 4, rb = r & 15, ks = k >> 4, kr = k & 15;
    int lane_f = ((rb & 7) << 2) | ((kr & 7) >> 1);
    int q = ((kr >> 3) << 1) | (rb >> 3);
    return (((bm * 16 + ks) * 33 + lane_f) << 2) + q;
}

// ---- pre-pack: weights fp32 -> fp16x2 fragment-ordered image (256 KB) ----
__global__ void pack_weights(const float* __restrict__ wxi, const float* __restrict__ wxf,
                             const float* __restrict__ wxg, const float* __restrict__ wxo,
                             const float* __restrict__ whi, const float* __restrict__ whf,
                             const float* __restrict__ whg, const float* __restrict__ who) {
    const float* wx[4] = {wxi, wxf, wxg, wxo};
    const float* wh[4] = {whi, whf, whg, who};
    int idx = blockIdx.x * blockDim.x + threadIdx.x;  // 0..65535
    int wq = idx & 3;
    int lane = (idx >> 2) & 31;
    int gp = (idx >> 7) & 1;
    int wN = (idx >> 8) & 7;
    int ks = (idx >> 11) & 15;
    int half = (idx >> 15) & 1;
    int g = 2 * gp + (wq >> 1);
    int bsel = wq & 1;
    int n = half * 64 + wN * 8 + (lane >> 2);
    int k0 = ks * 16 + 2 * (lane & 3) + bsel * 8;
    const float* w = (k0 < 128) ? wx[g] : wh[g];
    int kk = k0 & 127;
    float lo = w[(size_t)kk * HDIM + n];
    float hi = w[(size_t)(kk + 1) * HDIM + n];
    g_wpack[idx] = packh2(lo, hi);
}

// Issue cp.async group for raw A of tile j into slot (32 KB), then commit.
DEVINL void issue_rawA(int slot, long long row0, uint32_t smem_u32, int tid,
                       const float* __restrict__ x, const float* __restrict__ h) {
    const uint32_t dst = smem_u32 + (uint32_t)((SW_RAW + slot * RAW_SLOT) * 4);
#pragma unroll
    for (int i = 0; i < 4; i++) {
        int l = i * THREADS + tid;  // 16B line 0..2047
        int r = l >> 6;
        int c = (l & 63) * 4;
        const float* gsrc = (c < 128) ? (x + (row0 + r) * HDIM + c)
                                      : (h + (row0 + r) * HDIM + (c - 128));
        cp16(dst + l * 16, gsrc);
    }
    cp_commit();
}

__global__ void __launch_bounds__(THREADS, 1)
lstm_kernel(const float* __restrict__ x, const float* __restrict__ hprev,
            const float* __restrict__ cprev,
            const float* __restrict__ bi, const float* __restrict__ bf,
            const float* __restrict__ bg, const float* __restrict__ bo,
            float* __restrict__ outh, float* __restrict__ outc, int writeC) {
    extern __shared__ float sm[];
    uint32_t* smw = reinterpret_cast<uint32_t*>(sm);
    const int tid = threadIdx.x;
    const int lane = tid & 31;
    const int wid = tid >> 5;
    const int wM = wid >> 3;  // 0..1 (16 rows each)
    const int wN = wid & 7;   // 0..7 (8 h-cols x 4 gates each)
    const int cidx = blockIdx.x >> 1;  // 0..73
    const int half = blockIdx.x & 1;
    const uint32_t smem_u32 = (uint32_t)__cvta_generic_to_shared(sm);

    // First tile's raw A, then the resident B half image (128 KB).
    int j0 = cidx;
    issue_rawA(0, (long long)j0 * M_TILE, smem_u32, tid, x, hprev);
    {
        const uint32_t bdst = smem_u32 + (uint32_t)(SW_B * 4);
        const uint32_t* src = g_wpack + half * B_WORDS;
#pragma unroll
        for (int i = 0; i < 16; i++) {
            int l = i * THREADS + tid;  // 16B line 0..8191
            cp16(bdst + l * 16, src + l * 4);
        }
        cp_commit();
    }

    // biases for this half: [i|f|g|o] x 64 cols
    if (tid < 256) {
        int g = tid >> 6, c = tid & 63;
        const float* bsrc = (g == 0) ? bi : (g == 1) ? bf : (g == 2) ? bg : bo;
        sm[SW_BIAS + tid] = bsrc[half * 64 + c];
    }

    const uint4* apack = reinterpret_cast<const uint4*>(smw + SW_A);
    const uint4* bpk = reinterpret_cast<const uint4*>(smw + SW_B);
    const float* bsm = sm + SW_BIAS;

    const int rl0 = wM * 16 + (lane >> 2);
    const int nloc0 = wN * 8 + 2 * (lane & 3);
    const int n = half * 64 + nloc0;

    int slot = 0;
#pragma unroll 1
    for (int j = j0; j < NTILES; j += CPAIR) {
        const long long row0 = (long long)j * M_TILE;

        // Wait for everything pending (raw[j]; also B on the first iter).
        asm volatile("cp.async.wait_group 0;" ::: "memory");
        __syncthreads();

        // Convert raw fp32 -> packed fp16 A fragments (32 rows x 256 k).
        {
            const float* raw = sm + SW_RAW + slot * RAW_SLOT;
#pragma unroll
            for (int q = 0; q < 8; q++) {
                int p = q * THREADS + tid;  // float2 index 0..4095
                int r = p >> 7;
                int kp = (p & 127) * 2;
                float2 f2 = *reinterpret_cast<const float2*>(raw + r * 256 + kp);
                smw[SW_A + widx(r, kp)] = packh2(f2.x, f2.y);
            }
        }
        __syncthreads();

        // Prefetch next tile's raw A into the other slot (in flight during
        // compute + epilogue of this tile).
        if (j + CPAIR < NTILES)
            issue_rawA(slot ^ 1, (long long)(j + CPAIR) * M_TILE, smem_u32, tid,
                       x, hprev);

        // Prefetch this tile's c_prev into registers (hidden by compute).
        float2 cp0 = *reinterpret_cast<const float2*>(cprev + (row0 + rl0) * HDIM + n);
        float2 cp1 = *reinterpret_cast<const float2*>(cprev + (row0 + rl0 + 8) * HDIM + n);

        // Compute: 16 k-steps, 4 HMMA each (gates i,f,g,o for 8 h-cols).
        float acc[4][4];
#pragma unroll
        for (int g = 0; g < 4; g++)
#pragma unroll
            for (int q = 0; q < 4; q++) acc[g][q] = 0.0f;

#pragma unroll
        for (int ks = 0; ks < 16; ks++) {
            uint4 a = apack[(wM * 16 + ks) * 33 + lane];
            const uint4* bp = bpk + (ks * 8 + wN) * 64;
            uint4 b01 = bp[lane];
            uint4 b23 = bp[32 + lane];
            mma16(acc[0], a, b01.x, b01.y);
            mma16(acc[1], a, b01.z, b01.w);
            mma16(acc[2], a, b23.x, b23.y);
            mma16(acc[3], a, b23.z, b23.w);
        }

        // Epilogue: 2 rows x 2 cols per thread.
#pragma unroll
        for (int rh = 0; rh < 2; rh++) {
            const long long m = row0 + rl0 + rh * 8;
            const float2 cp2 = rh ? cp1 : cp0;
            float hv[2], cv[2];
#pragma unroll
            for (int col = 0; col < 2; col++) {
                const int nl = nloc0 + col;
                float ai = acc[0][rh * 2 + col] + bsm[nl];
                float af = acc[1][rh * 2 + col] + bsm[64 + nl];
                float ag = acc[2][rh * 2 + col] + bsm[128 + nl];
                float ao = acc[3][rh * 2 + col] + bsm[192 + nl];
                float ig = sigf(ai);
                float fg = sigf(af);
                float og = sigf(ao);
                float gg = tanhfast(ag);
                float cpv = (col == 0) ? cp2.x : cp2.y;
                float ct = fg * cpv + ig * gg;
                cv[col] = ct;
                hv[col] = og * tanhfast(ct);
            }
            *reinterpret_cast<float2*>(outh + m * HDIM + n) =
                make_float2(hv[0], hv[1]);
            if (writeC) {
                *reinterpret_cast<float2*>(outc + m * HDIM + n) =
                    make_float2(cv[0], cv[1]);
            }
        }

        slot ^= 1;
    }
}

}  // namespace

extern "C" void kernel_launch(void* const* d_in, const int* in_sizes, int n_in,
                              void* d_out, int out_size) {
    (void)in_sizes; (void)n_in;
    cudaFuncSetAttribute(lstm_kernel, cudaFuncAttributeMaxDynamicSharedMemorySize,
                         SMEM_BYTES);
    const float* x     = (const float*)d_in[0];
    const float* hprev = (const float*)d_in[1];
    const float* cprev = (const float*)d_in[2];
    const float* wxi   = (const float*)d_in[3];
    const float* wxf   = (const float*)d_in[4];
    const float* wxg   = (const float*)d_in[5];
    const float* wxo   = (const float*)d_in[6];
    const float* whi   = (const float*)d_in[7];
    const float* whf   = (const float*)d_in[8];
    const float* whg   = (const float*)d_in[9];
    const float* who   = (const float*)d_in[10];
    const float* bi    = (const float*)d_in[11];
    const float* bf    = (const float*)d_in[12];
    const float* bg    = (const float*)d_in[13];
    const float* bo    = (const float*)d_in[14];

    float* outh = (float*)d_out;
    const long long need2 = 2LL * BH;
    int writeC = ((long long)out_size >= need2) ? 1 : 0;
    float* outc = outh + BH;

    pack_weights<<<256, 256>>>(wxi, wxf, wxg, wxo, whi, whf, whg, who);
    lstm_kernel<<<GRID, THREADS, SMEM_BYTES>>>(
        x, hprev, cprev, bi, bf, bg, bo, outh, outc, writeC);
}

// round 17
// speedup vs baseline: 1.2405x; 1.2405x over previous
#include <cuda_runtime.h>
#include <cuda_fp16.h>
#include <cstdint>

#define DEVINL __device__ __forceinline__

namespace {

constexpr int HDIM = 128;
constexpr long long BROWS = 131072;
constexpr long long BH = BROWS * (long long)HDIM;
constexpr int THREADS = 256;
constexpr int M_TILE = 64;
constexpr int GRID = (int)(BROWS / M_TILE) * 2;  // 4096 (mtile x half)

// smem word (uint32) offsets
constexpr int SW_BIAS = 0;                      // 256 words (this half's 4x64)
constexpr int SW_A = 256;                       // packed A frags: 4bm*16ks*33 uint4
constexpr int A_WORDS = 4 * 16 * 33 * 4;        // 8448
constexpr int SW_RAW = SW_A + A_WORDS;          // 8704; 4 slots x 1024 words fp32
constexpr int RAW_SLOT = 1024;
constexpr int SW_B = SW_RAW + 4 * RAW_SLOT;     // 12800; 6 ks-slots x 2048 words
constexpr int B_SLOT = 2048;
constexpr int SMEM_WORDS = SW_B + 6 * B_SLOT;   // 25088
constexpr int SMEM_BYTES = SMEM_WORDS * 4;      // 100352 -> 2 CTAs/SM

// Pre-packed weights, fragment order:
// word idx = ((((half*16+ks)*8+wN)*2+gp)*32+lane)*4 + wq
//   gp packs gates {2gp, 2gp+1}; wq = gsel*2 + bsel (b0/b1 k8-halves)
__device__ uint32_t g_wpack[2 * 16 * 8 * 2 * 32 * 4];  // 65536 words, 256 KB

DEVINL void cp16(uint32_t saddr, const void* gaddr) {
    asm volatile("cp.async.cg.shared.global [%0], [%1], 16;"
                 :: "r"(saddr), "l"(gaddr) : "memory");
}
DEVINL void cp_commit() { asm volatile("cp.async.commit_group;" ::: "memory"); }

DEVINL uint32_t packh2(float lo, float hi) {
    __half2 h = __floats2half2_rn(lo, hi);
    return *reinterpret_cast<uint32_t*>(&h);
}

DEVINL void mma16(float* d, const uint4& a, uint32_t b0, uint32_t b1) {
    asm volatile(
        "mma.sync.aligned.m16n8k16.row.col.f32.f16.f16.f32 "
        "{%0,%1,%2,%3}, {%4,%5,%6,%7}, {%8,%9}, {%0,%1,%2,%3};"
        : "+f"(d[0]), "+f"(d[1]), "+f"(d[2]), "+f"(d[3])
        : "r"(a.x), "r"(a.y), "r"(a.z), "r"(a.w), "r"(b0), "r"(b1));
}

DEVINL float sigf(float x) {
    return __fdividef(1.0f, 1.0f + __expf(-x));
}
DEVINL float tanhfast(float x) {
    return __fdividef(2.0f, 1.0f + __expf(-2.0f * x)) - 1.0f;
}

// Packed A word index for fp16x2 word holding (r,k),(r,k+1), k even; r 0..63.
// Consumer reads uint4 at ((bm*16 + ks)*33 + lane), bm = r>>4 in 0..3.
DEVINL int widx(int r, int k) {
    int bm = r >> 4, rb = r & 15, ks = k >> 4, kr = k & 15;
    int lane_f = ((rb & 7) << 2) | ((kr & 7) >> 1);
    int q = ((kr >> 3) << 1) | (rb >> 3);
    return (((bm * 16 + ks) * 33 + lane_f) << 2) + q;
}

// ---- pre-pack: weights fp32 -> fp16x2 fragment-ordered image (256 KB) ----
__global__ void pack_weights(const float* __restrict__ wxi, const float* __restrict__ wxf,
                             const float* __restrict__ wxg, const float* __restrict__ wxo,
                             const float* __restrict__ whi, const float* __restrict__ whf,
                             const float* __restrict__ whg, const float* __restrict__ who) {
    const float* wx[4] = {wxi, wxf, wxg, wxo};
    const float* wh[4] = {whi, whf, whg, who};
    int idx = blockIdx.x * blockDim.x + threadIdx.x;  // 0..65535
    int wq = idx & 3;
    int lane = (idx >> 2) & 31;
    int gp = (idx >> 7) & 1;
    int wN = (idx >> 8) & 7;
    int ks = (idx >> 11) & 15;
    int half = (idx >> 15) & 1;
    int g = 2 * gp + (wq >> 1);
    int bsel = wq & 1;
    int n = half * 64 + wN * 8 + (lane >> 2);
    int k0 = ks * 16 + 2 * (lane & 3) + bsel * 8;
    const float* w = (k0 < 128) ? wx[g] : wh[g];
    int kk = k0 & 127;
    float lo = w[(size_t)kk * HDIM + n];
    float hi = w[(size_t)(kk + 1) * HDIM + n];
    g_wpack[idx] = packh2(lo, hi);
}

// Issue cp.async group for k-step ks: B[ks] (8 KB, this half) + raw A[ks] (4 KB).
DEVINL void issue_group(int ks, int half, uint32_t smem_u32, int tid,
                        const float* __restrict__ x, const float* __restrict__ h,
                        long long row0) {
    const uint32_t bdst = smem_u32 + (uint32_t)((SW_B + (ks % 6) * B_SLOT) * 4);
    const uint32_t* src = g_wpack + (half * 16 + ks) * 2048;
    cp16(bdst + tid * 16, src + tid * 4);
    cp16(bdst + (tid + 256) * 16, src + (tid + 256) * 4);
    {
        int r = tid >> 2, c4 = tid & 3;
        const float* gsrc =
            ((ks < 8) ? x : h) + (row0 + r) * HDIM + (ks & 7) * 16 + c4 * 4;
        cp16(smem_u32 + (uint32_t)((SW_RAW + (ks % 4) * RAW_SLOT) * 4) + tid * 16,
             gsrc);
    }
    cp_commit();
}

__global__ void __launch_bounds__(THREADS, 2)
lstm_kernel(const float* __restrict__ x, const float* __restrict__ hprev,
            const float* __restrict__ cprev,
            const float* __restrict__ bi, const float* __restrict__ bf,
            const float* __restrict__ bg, const float* __restrict__ bo,
            float* __restrict__ outh, float* __restrict__ outc, int writeC) {
    extern __shared__ float sm[];
    uint32_t* smw = reinterpret_cast<uint32_t*>(sm);
    const int tid = threadIdx.x;
    const int lane = tid & 31;
    const int wN = tid >> 5;  // 0..7 (8 h-cols x 4 gates each)
    const int mtile = blockIdx.x >> 1;
    const int half = blockIdx.x & 1;
    const long long row0 = (long long)mtile * M_TILE;
    const uint32_t smem_u32 = (uint32_t)__cvta_generic_to_shared(sm);

    // Prologue: 4 in-flight groups.
    issue_group(0, half, smem_u32, tid, x, hprev, row0);
    issue_group(1, half, smem_u32, tid, x, hprev, row0);
    issue_group(2, half, smem_u32, tid, x, hprev, row0);
    issue_group(3, half, smem_u32, tid, x, hprev, row0);

    // biases for this half: [i|f|g|o] x 64 cols
    {
        int g = tid >> 6, c = tid & 63;
        const float* bsrc = (g == 0) ? bi : (g == 1) ? bf : (g == 2) ? bg : bo;
        sm[SW_BIAS + tid] = bsrc[half * 64 + c];
    }

    float acc[4][4][4];
#pragma unroll
    for (int mi = 0; mi < 4; mi++)
#pragma unroll
        for (int g = 0; g < 4; g++)
#pragma unroll
            for (int q = 0; q < 4; q++) acc[mi][g][q] = 0.0f;

    // Wait for group 0 (raw A[0]); convert packed A[0].
    asm volatile("cp.async.wait_group 3;" ::: "memory");
    __syncthreads();
#pragma unroll
    for (int j = 0; j < 2; j++) {
        int p = j * THREADS + tid;  // float2 index 0..511
        int r = p >> 3, kp = (p & 7) * 2;
        float2 f2 = *reinterpret_cast<const float2*>(sm + SW_RAW + r * 16 + kp);
        smw[SW_A + widx(r, kp)] = packh2(f2.x, f2.y);
    }

    const uint4* apack = reinterpret_cast<const uint4*>(smw + SW_A);

    // Mainloop: ONE barrier per ks; convert(ks+1) overlapped with compute(ks).
#define STEP(ks, W)                                                            \
    {                                                                          \
        asm volatile("cp.async.wait_group %0;" :: "n"(W) : "memory");          \
        __syncthreads();                                                       \
        if ((ks) + 4 < 16)                                                     \
            issue_group((ks) + 4, half, smem_u32, tid, x, hprev, row0);        \
        if ((ks) + 1 < 16) {                                                   \
            const float* raw = sm + SW_RAW + (((ks) + 1) % 4) * RAW_SLOT;      \
            _Pragma("unroll")                                                  \
            for (int j = 0; j < 2; j++) {                                      \
                int p = j * THREADS + tid;                                     \
                int r = p >> 3, kp = (p & 7) * 2;                              \
                float2 f2 =                                                    \
                    *reinterpret_cast<const float2*>(raw + r * 16 + kp);       \
                smw[SW_A + widx(r, ((ks) + 1) * 16 + kp)] =                    \
                    packh2(f2.x, f2.y);                                        \
            }                                                                  \
        }                                                                      \
        {                                                                      \
            uint4 a0 = apack[(0 * 16 + (ks)) * 33 + lane];                     \
            uint4 a1 = apack[(1 * 16 + (ks)) * 33 + lane];                     \
            uint4 a2 = apack[(2 * 16 + (ks)) * 33 + lane];                     \
            uint4 a3 = apack[(3 * 16 + (ks)) * 33 + lane];                     \
            const uint4* bp = reinterpret_cast<const uint4*>(                  \
                smw + SW_B + ((ks) % 6) * B_SLOT);                             \
            uint4 bv01 = bp[(wN * 2 + 0) * 32 + lane];                         \
            uint4 bv23 = bp[(wN * 2 + 1) * 32 + lane];                         \
            mma16(acc[0][0], a0, bv01.x, bv01.y);                              \
            mma16(acc[0][1], a0, bv01.z, bv01.w);                              \
            mma16(acc[0][2], a0, bv23.x, bv23.y);                              \
            mma16(acc[0][3], a0, bv23.z, bv23.w);                              \
            mma16(acc[1][0], a1, bv01.x, bv01.y);                              \
            mma16(acc[1][1], a1, bv01.z, bv01.w);                              \
            mma16(acc[1][2], a1, bv23.x, bv23.y);                              \
            mma16(acc[1][3], a1, bv23.z, bv23.w);                              \
            mma16(acc[2][0], a2, bv01.x, bv01.y);                              \
            mma16(acc[2][1], a2, bv01.z, bv01.w);                              \
            mma16(acc[2][2], a2, bv23.x, bv23.y);                              \
            mma16(acc[2][3], a2, bv23.z, bv23.w);                              \
            mma16(acc[3][0], a3, bv01.x, bv01.y);                              \
            mma16(acc[3][1], a3, bv01.z, bv01.w);                              \
            mma16(acc[3][2], a3, bv23.x, bv23.y);                              \
            mma16(acc[3][3], a3, bv23.z, bv23.w);                              \
        }                                                                      \
    }

    STEP(0, 2)  STEP(1, 2)  STEP(2, 2)  STEP(3, 2)
    STEP(4, 2)  STEP(5, 2)  STEP(6, 2)  STEP(7, 2)
    STEP(8, 2)  STEP(9, 2)  STEP(10, 2) STEP(11, 2)
    STEP(12, 2) STEP(13, 1) STEP(14, 0) STEP(15, 0)
#undef STEP

    // Epilogue: warp owns h-cols [half*64+wN*8, +8), all 4 gates, 64 rows.
    const float* bsm = sm + SW_BIAS;
    const int nl0 = wN * 8 + 2 * (lane & 3);
    const int n = half * 64 + nl0;
#pragma unroll
    for (int mi = 0; mi < 4; mi++) {
#pragma unroll
        for (int rh = 0; rh < 2; rh++) {
            const long long m = row0 + mi * 16 + (lane >> 2) + rh * 8;
            float2 cp2 = *reinterpret_cast<const float2*>(cprev + m * HDIM + n);
            float hv[2], cv[2];
#pragma unroll
            for (int col = 0; col < 2; col++) {
                const int nl = nl0 + col;
                float ai = acc[mi][0][rh * 2 + col] + bsm[nl];
                float af = acc[mi][1][rh * 2 + col] + bsm[64 + nl];
                float ag = acc[mi][2][rh * 2 + col] + bsm[128 + nl];
                float ao = acc[mi][3][rh * 2 + col] + bsm[192 + nl];
                float ig = sigf(ai);
                float fg = sigf(af);
                float og = sigf(ao);
                float gg = tanhfast(ag);
                float cpv = (col == 0) ? cp2.x : cp2.y;
                float ct = fg * cpv + ig * gg;
                cv[col] = ct;
                hv[col] = og * tanhfast(ct);
            }
            *reinterpret_cast<float2*>(outh + m * HDIM + n) =
                make_float2(hv[0], hv[1]);
            if (writeC) {
                *reinterpret_cast<float2*>(outc + m * HDIM + n) =
                    make_float2(cv[0], cv[1]);
            }
        }
    }
}

}  // namespace

extern "C" void kernel_launch(void* const* d_in, const int* in_sizes, int n_in,
                              void* d_out, int out_size) {
    (void)in_sizes; (void)n_in;
    cudaFuncSetAttribute(lstm_kernel, cudaFuncAttributeMaxDynamicSharedMemorySize,
                         SMEM_BYTES);
    const float* x     = (const float*)d_in[0];
    const float* hprev = (const float*)d_in[1];
    const float* cprev = (const float*)d_in[2];
    const float* wxi   = (const float*)d_in[3];
    const float* wxf   = (const float*)d_in[4];
    const float* wxg   = (const float*)d_in[5];
    const float* wxo   = (const float*)d_in[6];
    const float* whi   = (const float*)d_in[7];
    const float* whf   = (const float*)d_in[8];
    const float* whg   = (const float*)d_in[9];
    const float* who   = (const float*)d_in[10];
    const float* bi    = (const float*)d_in[11];
    const float* bf    = (const float*)d_in[12];
    const float* bg    = (const float*)d_in[13];
    const float* bo    = (const float*)d_in[14];

    float* outh = (float*)d_out;
    const long long need2 = 2LL * BH;
    int writeC = ((long long)out_size >= need2) ? 1 : 0;
    float* outc = outh + BH;

    pack_weights<<<256, 256>>>(wxi, wxf, wxg, wxo, whi, whf, whg, who);
    lstm_kernel<<<GRID, THREADS, SMEM_BYTES>>>(
        x, hprev, cprev, bi, bf, bg, bo, outh, outc, writeC);
}